// round 14
// baseline (speedup 1.0000x reference)
#include <cuda_runtime.h>
#include <cstdint>

// SpikingNeuronLayer — r13: bitwise-frozen numerics (r12 rel_err=0.0), now fast.
// Numerics contract (DO NOT CHANGE):
//   p1 = fused ascending fp32 chain k in [0,512), fresh acc
//   p2 = fused ascending fp32 chain k in [512,1024), fresh acc
//   I  = fl( fl(p1+p2) + b )
//   scan: mem = fma(alpha, mem, I_t); s = mem>=1; mem *= (1-s)   [fused]
// Speed changes (bitwise-neutral):
//   - GEMM inner loop uses packed fma.rn.f32x2 (FFMA2): 2 independent
//     correctly-rounded fp32 FMAs per instruction, pairing adjacent j outputs.
//     Per-element k-order and rounding sequence unchanged.
//   - Scan uses a depth-8 register prefetch pipeline (MLP 8) to hide DRAM/L2
//     latency; arithmetic untouched.

namespace {
constexpr int BATCH  = 64;
constexpr int TSTEPS = 512;
constexpr int INDIM  = 1024;
constexpr int HID    = 1024;
constexpr int M      = BATCH * TSTEPS;   // 32768
constexpr int KSPLIT = 512;              // Eigen gebp kc panel size (confirmed)
constexpr float ALPHA = 0.9512294245007140f;  // exp(-1/20) rounded to f32

constexpr int BM = 128, BN = 128, BK = 16;
}

// Scratch for the GEMM output I[M, HID] (134 MB). Static device global: no allocs.
__device__ float g_I[(size_t)M * HID];

// --- packed f32x2 helpers (each lane = exact IEEE fp32 op, .rn) -------------
#define PACK_SPLAT(dst, v) \
    asm("mov.b64 %0, {%1, %1};" : "=l"(dst) : "f"(v))
#define FMA2(d, a, b, c) \
    asm("fma.rn.f32x2 %0, %1, %2, %3;" : "=l"(d) : "l"(a), "l"(b), "l"(c))
#define UNPACK2(lo, hi, src) \
    asm("mov.b64 {%0, %1}, %2;" : "=f"(lo), "=f"(hi) : "l"(src))

__global__ __launch_bounds__(256, 1)
void gemm_bias_kernel(const float* __restrict__ A,   // x  [M, INDIM]
                      const float* __restrict__ B,   // W  [HID, INDIM]
                      const float* __restrict__ bias)
{
    __shared__ float As[BK][BM + 4];
    __shared__ float Bs[BK][BN + 4];

    const int bm  = blockIdx.y * BM;
    const int bn  = blockIdx.x * BN;
    const int tid = threadIdx.x;

    const int tcol = tid & 15;   // across N (8 outputs = 4 j-pairs)
    const int trow = tid >> 4;   // across M (8 outputs)

    const int lrow = tid >> 2;          // 0..63
    const int lcol = (tid & 3) << 2;    // 0,4,8,12

    // acc pairs: [i][jp] covers outputs (i, 2jp) and (i, 2jp+1).
    // Panel 1 (k<512) and panel 2 (k>=512) kept in separate fresh accumulators.
    unsigned long long accA[8][4], accB[8][4];
#pragma unroll
    for (int i = 0; i < 8; i++)
#pragma unroll
        for (int jp = 0; jp < 4; jp++) { accA[i][jp] = 0ull; accB[i][jp] = 0ull; }

    const float* Ap = A + (size_t)bm * INDIM;
    const float* Bp = B + (size_t)bn * INDIM;

    for (int k0 = 0; k0 < INDIM; k0 += BK) {
        float4 a0 = *(const float4*)(Ap + (size_t)lrow        * INDIM + k0 + lcol);
        float4 a1 = *(const float4*)(Ap + (size_t)(lrow + 64) * INDIM + k0 + lcol);
        float4 b0 = *(const float4*)(Bp + (size_t)lrow        * INDIM + k0 + lcol);
        float4 b1 = *(const float4*)(Bp + (size_t)(lrow + 64) * INDIM + k0 + lcol);

        As[lcol + 0][lrow] = a0.x; As[lcol + 1][lrow] = a0.y;
        As[lcol + 2][lrow] = a0.z; As[lcol + 3][lrow] = a0.w;
        As[lcol + 0][lrow + 64] = a1.x; As[lcol + 1][lrow + 64] = a1.y;
        As[lcol + 2][lrow + 64] = a1.z; As[lcol + 3][lrow + 64] = a1.w;

        Bs[lcol + 0][lrow] = b0.x; Bs[lcol + 1][lrow] = b0.y;
        Bs[lcol + 2][lrow] = b0.z; Bs[lcol + 3][lrow] = b0.w;
        Bs[lcol + 0][lrow + 64] = b1.x; Bs[lcol + 1][lrow + 64] = b1.y;
        Bs[lcol + 2][lrow + 64] = b1.z; Bs[lcol + 3][lrow + 64] = b1.w;

        __syncthreads();

        const bool panel1 = (k0 < KSPLIT);   // uniform per tile
#pragma unroll
        for (int kk = 0; kk < BK; kk++) {
            float ar[8];
            *(float4*)&ar[0] = *(const float4*)&As[kk][trow * 8];
            *(float4*)&ar[4] = *(const float4*)&As[kk][trow * 8 + 4];

            // B j-pairs as direct 64-bit shared loads (32B-aligned offsets)
            unsigned long long bp[4];
            bp[0] = *(const unsigned long long*)&Bs[kk][tcol * 8 + 0];
            bp[1] = *(const unsigned long long*)&Bs[kk][tcol * 8 + 2];
            bp[2] = *(const unsigned long long*)&Bs[kk][tcol * 8 + 4];
            bp[3] = *(const unsigned long long*)&Bs[kk][tcol * 8 + 6];

            unsigned long long ap[8];
#pragma unroll
            for (int i = 0; i < 8; i++) PACK_SPLAT(ap[i], ar[i]);

            if (panel1) {
#pragma unroll
                for (int i = 0; i < 8; i++)
#pragma unroll
                    for (int jp = 0; jp < 4; jp++)
                        FMA2(accA[i][jp], ap[i], bp[jp], accA[i][jp]);
            } else {
#pragma unroll
                for (int i = 0; i < 8; i++)
#pragma unroll
                    for (int jp = 0; jp < 4; jp++)
                        FMA2(accB[i][jp], ap[i], bp[jp], accB[i][jp]);
            }
        }
        __syncthreads();
    }

    // epilogue: dot = fl(p1+p2); I = fl(dot + b)  — identical to r12
    float bj[8];
#pragma unroll
    for (int j = 0; j < 8; j++) bj[j] = bias[bn + tcol * 8 + j];

#pragma unroll
    for (int i = 0; i < 8; i++) {
        const int row = bm + trow * 8 + i;
        float* out = g_I + (size_t)row * HID + bn + tcol * 8;
        float p1[8], p2[8];
#pragma unroll
        for (int jp = 0; jp < 4; jp++) {
            UNPACK2(p1[2 * jp], p1[2 * jp + 1], accA[i][jp]);
            UNPACK2(p2[2 * jp], p2[2 * jp + 1], accB[i][jp]);
        }
#pragma unroll
        for (int j = 0; j < 8; j += 4) {
            float4 v;
            v.x = __fadd_rn(__fadd_rn(p1[j + 0], p2[j + 0]), bj[j + 0]);
            v.y = __fadd_rn(__fadd_rn(p1[j + 1], p2[j + 1]), bj[j + 1]);
            v.z = __fadd_rn(__fadd_rn(p1[j + 2], p2[j + 2]), bj[j + 2]);
            v.w = __fadd_rn(__fadd_rn(p1[j + 3], p2[j + 3]), bj[j + 3]);
            *(float4*)(out + j) = v;
        }
    }
}

__global__ __launch_bounds__(256)
void lif_scan_kernel(float* __restrict__ spikes,    // [BATCH, TSTEPS, HID]
                     float* __restrict__ mem_final) // [BATCH, HID]
{
    const int idx = blockIdx.x * blockDim.x + threadIdx.x;  // 0 .. BATCH*HID-1
    const int b = idx / HID;
    const int h = idx - b * HID;

    const float* ip = g_I    + (size_t)b * TSTEPS * HID + h;
    float*       sp = spikes + (size_t)b * TSTEPS * HID + h;

    // depth-8 register prefetch pipeline: hides load latency (MLP=8),
    // arithmetic chain untouched (bitwise identical to r12).
    constexpr int PF = 8;
    float buf[PF];
#pragma unroll
    for (int t = 0; t < PF; t++) buf[t] = __ldg(&ip[(size_t)t * HID]);

    float mem = 0.0f;
    for (int t0 = 0; t0 < TSTEPS; t0 += PF) {
#pragma unroll
        for (int u = 0; u < PF; u++) {
            const int t = t0 + u;
            const float cur = buf[u];
            if (t + PF < TSTEPS) buf[u] = __ldg(&ip[(size_t)(t + PF) * HID]);
            mem = __fmaf_rn(ALPHA, mem, cur);
            const float s = (mem >= 1.0f) ? 1.0f : 0.0f;
            sp[(size_t)t * HID] = s;
            mem = mem * (1.0f - s);   // exact: multiplies by 0.0 or 1.0
        }
    }
    mem_final[idx] = mem;
}

extern "C" void kernel_launch(void* const* d_in, const int* in_sizes, int n_in,
                              void* d_out, int out_size)
{
    (void)in_sizes; (void)n_in; (void)out_size;
    const float* x    = (const float*)d_in[0];
    const float* W    = (const float*)d_in[1];
    const float* bias = (const float*)d_in[2];

    float* out    = (float*)d_out;
    float* spikes = out;                              // [B,T,H]
    float* memf   = out + (size_t)M * HID;            // [B,H]

    dim3 grid(HID / BN, M / BM);   // (8, 256)
    gemm_bias_kernel<<<grid, 256>>>(x, W, bias);

    lif_scan_kernel<<<(BATCH * HID) / 256, 256>>>(spikes, memf);
}